// round 11
// baseline (speedup 1.0000x reference)
#include <cuda_runtime.h>

#define NRES 384
#define NATM 640
#define NCEP 4
#define TOK  1024
#define NROWS 2944
#define C1   256
#define C2   128
#define AC   32
#define NH   8
#define LOG2E_F 1.4426950408889634f
#define BIAS_SCALE 0.2550316248700962f   // (1/sqrt(32))*LOG2E

typedef unsigned long long ull;

__device__ __align__(16) float g_xn[NROWS * C1];
__device__ __align__(16) float g_qh[NH * NROWS * AC];
__device__ __align__(16) float g_kh[NH * NROWS * AC];
__device__ __align__(16) float g_vh[NH * NROWS * AC];
__device__ __align__(16) float g_bias[(size_t)NH * TOK * TOK];
// PV scratch, head-major: [h][q][c] / [m][h][q][c] so k_attn can store float4
__device__ __align__(16) float g_resPV[NH * NRES * AC];
__device__ __align__(16) float g_atmPV[NCEP * NH * NRES * AC];
__device__ __align__(16) float g_ligPV[NCEP * NH * NATM * AC];

__device__ __forceinline__ void ffma2(ull& d, ull a, ull b) {
    asm("fma.rn.f32x2 %0, %1, %2, %0;" : "+l"(d) : "l"(a), "l"(b));
}
__device__ __forceinline__ ull fmul2(ull a, ull b) {
    ull d; asm("mul.rn.f32x2 %0, %1, %2;" : "=l"(d) : "l"(a), "l"(b)); return d;
}
__device__ __forceinline__ ull pack2(float x, float y) {
    ull d; asm("mov.b64 %0, {%1, %2};" : "=l"(d) : "f"(x), "f"(y)); return d;
}
__device__ __forceinline__ float2 unpack2(ull v) {
    float2 r; asm("mov.b64 {%0, %1}, %2;" : "=f"(r.x), "=f"(r.y) : "l"(v)); return r;
}
__device__ __forceinline__ float ex2(float x) {
    float y; asm("ex2.approx.ftz.f32 %0, %1;" : "=f"(y) : "f"(x)); return y;
}

// ---------------- K0: layernorm ----------------
__global__ __launch_bounds__(256) void k_ln(const float* __restrict__ rec,
                                            const float* __restrict__ lig,
                                            const float* __restrict__ gam,
                                            const float* __restrict__ bet) {
    int row = blockIdx.x, t = threadIdx.x;
    const float* x = (row < NRES) ? rec + (size_t)row * C1 : lig + (size_t)(row - NRES) * C1;
    float v = x[t];
    __shared__ float red[8];
    __shared__ float s_mu, s_rstd;
    float s = v;
    #pragma unroll
    for (int o = 16; o; o >>= 1) s += __shfl_xor_sync(~0u, s, o);
    if ((t & 31) == 0) red[t >> 5] = s;
    __syncthreads();
    if (t == 0) { float tot = 0.f;
        #pragma unroll
        for (int i = 0; i < 8; i++) tot += red[i];
        s_mu = tot * (1.f / C1); }
    __syncthreads();
    float d = v - s_mu, q = d * d;
    #pragma unroll
    for (int o = 16; o; o >>= 1) q += __shfl_xor_sync(~0u, q, o);
    __syncthreads();
    if ((t & 31) == 0) red[t >> 5] = q;
    __syncthreads();
    if (t == 0) { float tot = 0.f;
        #pragma unroll
        for (int i = 0; i < 8; i++) tot += red[i];
        s_rstd = rsqrtf(tot * (1.f / C1) + 1e-5f); }
    __syncthreads();
    g_xn[(size_t)row * C1 + t] = d * s_rstd * gam[t] + bet[t];
}

// ---------------- K1: q/k/v projections ----------------
__global__ __launch_bounds__(256) void k_proj(const float* __restrict__ wrq, const float* __restrict__ wrk,
                                              const float* __restrict__ wrv, const float* __restrict__ wlq,
                                              const float* __restrict__ wlk, const float* __restrict__ wlv) {
    __shared__ __align__(16) float xs_t[C1][18];
    int tile = blockIdx.x, which = blockIdx.y, t = threadIdx.x;
    int row0 = tile * 16;
    bool isrec = row0 < NRES;
    const float* w; float* outb;
    if (which == 0)      { w = isrec ? wrq : wlq; outb = g_qh; }
    else if (which == 1) { w = isrec ? wrk : wlk; outb = g_kh; }
    else                 { w = isrec ? wrv : wlv; outb = g_vh; }

    const float4* src = (const float4*)(g_xn + (size_t)row0 * C1);
    #pragma unroll
    for (int k = 0; k < 4; k++) {
        int idx = k * 256 + t, r = idx >> 6, c4 = idx & 63;
        float4 v = src[idx];
        xs_t[4 * c4 + 0][r] = v.x; xs_t[4 * c4 + 1][r] = v.y;
        xs_t[4 * c4 + 2][r] = v.z; xs_t[4 * c4 + 3][r] = v.w;
    }
    __syncthreads();
    int o = t;
    ull acc[8];
    #pragma unroll
    for (int r2 = 0; r2 < 8; r2++) acc[r2] = 0ull;
    const float* wc = w + o;
    #pragma unroll 4
    for (int i = 0; i < C1; i++) {
        float wv = wc[(size_t)i * 256];
        ull w2 = pack2(wv, wv);
        #pragma unroll
        for (int r2 = 0; r2 < 8; r2++) ffma2(acc[r2], *(const ull*)&xs_t[i][2 * r2], w2);
    }
    float scale = (which == 0) ? LOG2E_F : 1.0f;
    int h = o & 7, c = o >> 3;
    float* ob = outb + ((size_t)h * NROWS + row0) * AC + c;
    #pragma unroll
    for (int r2 = 0; r2 < 8; r2++) {
        float2 a = unpack2(acc[r2]);
        ob[(size_t)(2 * r2) * AC] = a.x * scale;
        ob[(size_t)(2 * r2 + 1) * AC] = a.y * scale;
    }
}

// ---------------- K2: pair bias (key-major lanes: p read once per SM) ----------------
__global__ __launch_bounds__(256) void k_bias(const float* __restrict__ pair,
                                              const float* __restrict__ wrr, const float* __restrict__ wll,
                                              const float* __restrict__ wrl, const float* __restrict__ wlr) {
    __shared__ __align__(16) float4 ptile[2][32][32];   // [buf][key][chunk]
    __shared__ __align__(16) float wt[2][NH][132];      // padded: distinct banks per head
    int i = blockIdx.x, t = threadIdx.x;
    const float* wA = (i < NRES) ? wrr : wlr;     // keys < 384
    const float* wB = (i < NRES) ? wrl : wll;     // keys >= 384
    for (int idx = t; idx < 2 * NH * C2; idx += 256) {
        int q = idx >> 10, rem = idx & 1023, h = rem >> 7, c = rem & 127;
        wt[q][h][c] = (q ? wB : wA)[c * NH + h];
    }
    const float* pbase = pair + (size_t)i * TOK * C2;

    auto prefetch = [&](int tile, int buf) {
        #pragma unroll
        for (int k = 0; k < 4; k++) {
            int idx = k * 256 + t, j = idx >> 5, s4 = idx & 31;
            const float* src = pbase + (size_t)(tile * 32 + j) * C2 + s4 * 4;
            unsigned dst = (unsigned)__cvta_generic_to_shared(&ptile[buf][j][s4]);
            asm volatile("cp.async.cg.shared.global [%0], [%1], 16;" :: "r"(dst), "l"(src) : "memory");
        }
        asm volatile("cp.async.commit_group;" ::: "memory");
    };
    prefetch(0, 0);
    int h = t & 7, l = t >> 3;   // 8 lanes per key share every p-load (broadcast)
    for (int tile = 0; tile < 32; tile++) {
        int buf = tile & 1;
        if (tile + 1 < 32) { prefetch(tile + 1, buf ^ 1);
            asm volatile("cp.async.wait_group 1;" ::: "memory");
        } else { asm volatile("cp.async.wait_group 0;" ::: "memory"); }
        __syncthreads();
        int q = (tile < 12) ? 0 : 1;
        const ulonglong2* prow = (const ulonglong2*)&ptile[buf][l][0];
        const ulonglong2* wrow = (const ulonglong2*)&wt[q][h][0];
        ull acc = 0ull;
        #pragma unroll
        for (int s4 = 0; s4 < 32; s4++) {
            ulonglong2 p = prow[s4];
            ulonglong2 wv = wrow[s4];
            ffma2(acc, p.x, wv.x);
            ffma2(acc, p.y, wv.y);
        }
        float2 a = unpack2(acc);
        g_bias[((size_t)h * TOK + i) * TOK + tile * 32 + l] = (a.x + a.y) * BIAS_SCALE;
        __syncthreads();
    }
}

// ---------------- K3: attention (unified, 128 thr, 32-key tiles) ----------------
// MODE: 0 = PV into accA, 1 = PV into accR, 2 = logits only
template <int MODE>
__device__ __forceinline__ void attn_tile32(int t, bool dual, const ull (&q2)[16],
                                            float& mx, float& sm, ull (&accR)[16], ull (&accA)[16],
                                            const float (&ksm)[32][36], const float (&vsm)[32][36],
                                            const float4 (&bsm)[128][8]) {
    #pragma unroll
    for (int j4 = 0; j4 < 8; j4++) {
        float4 b4 = bsm[t][j4 ^ (t & 7)];
        float be[4] = {b4.x, b4.y, b4.z, b4.w};
        #pragma unroll
        for (int e = 0; e < 4; e++) {
            int j = j4 * 4 + e;
            const ulonglong2* kr = (const ulonglong2*)&ksm[j][0];
            ull d = 0ull;
            #pragma unroll
            for (int i2 = 0; i2 < 8; i2++) {
                ulonglong2 kk = kr[i2];
                ffma2(d, q2[2 * i2], kk.x);
                ffma2(d, q2[2 * i2 + 1], kk.y);
            }
            float2 dd = unpack2(d);
            float logit = dd.x + dd.y + be[e];
            if (logit > mx) {
                float sc = ex2(mx - logit);
                sm *= sc;
                ull sc2 = pack2(sc, sc);
                #pragma unroll
                for (int r = 0; r < 16; r++) accA[r] = fmul2(accA[r], sc2);
                if (dual) {
                    #pragma unroll
                    for (int r = 0; r < 16; r++) accR[r] = fmul2(accR[r], sc2);
                }
                mx = logit;
            }
            float p = ex2(logit - mx);
            sm += p;
            if (MODE != 2) {
                ull p2 = pack2(p, p);
                const ulonglong2* vr = (const ulonglong2*)&vsm[j][0];
                #pragma unroll
                for (int i2 = 0; i2 < 8; i2++) {
                    ulonglong2 vv = vr[i2];
                    if (MODE == 1) { ffma2(accR[2 * i2], p2, vv.x); ffma2(accR[2 * i2 + 1], p2, vv.y); }
                    else           { ffma2(accA[2 * i2], p2, vv.x); ffma2(accA[2 * i2 + 1], p2, vv.y); }
                }
            }
        }
    }
}

__device__ __forceinline__ void store_pv(float* dst4base, const ull (&acc)[16], float inv) {
    float4* d4 = (float4*)dst4base;
    #pragma unroll
    for (int j = 0; j < 8; j++) {
        float2 a = unpack2(acc[2 * j]);
        float2 b = unpack2(acc[2 * j + 1]);
        float4 o4 = make_float4(a.x * inv, a.y * inv, b.x * inv, b.y * inv);
        d4[j] = o4;
    }
}

__global__ __launch_bounds__(128) void k_attn() {
    __shared__ __align__(16) float ksm[32][36];
    __shared__ __align__(16) float vsm[32][36];
    __shared__ __align__(16) float4 bsm[128][8];
    int qt = blockIdx.x, h = blockIdx.y, m = blockIdx.z, t = threadIdx.x;
    bool resq = qt < 3;                       // qt 0..2: res queries; 3..7: atom queries
    int qtok = qt * 128 + t;
    int qrow = resq ? qtok : (NRES + m * NATM + (qtok - NRES));

    ull q2[16];
    {
        const ulonglong2* qp = (const ulonglong2*)(g_qh + ((size_t)h * NROWS + qrow) * AC);
        #pragma unroll
        for (int i = 0; i < 8; i++) { ulonglong2 u = qp[i]; q2[2 * i] = u.x; q2[2 * i + 1] = u.y; }
    }
    float mx = -1e30f, sm = 0.f;
    ull accA[16], accR[16];
    #pragma unroll
    for (int i = 0; i < 16; i++) { accA[i] = 0ull; accR[i] = 0ull; }
    bool dual = resq && (m == 0);
    const size_t bias_qbase = (size_t)h * TOK + qt * 128;

    for (int kt = 0; kt < 32; kt++) {
        // stage k/v: 32 rows x 8 float4, cooperative (8 lanes per contiguous row)
        #pragma unroll
        for (int it = 0; it < 2; it++) {
            int idx = it * 128 + t, row = idx >> 3, s4 = idx & 7;
            int ktok = kt * 32 + row;
            int krow = (ktok < NRES) ? ktok : (NRES + m * NATM + (ktok - NRES));
            *(float4*)&ksm[row][s4 * 4] = ((const float4*)(g_kh + ((size_t)h * NROWS + krow) * AC))[s4];
            *(float4*)&vsm[row][s4 * 4] = ((const float4*)(g_vh + ((size_t)h * NROWS + krow) * AC))[s4];
        }
        // stage bias: 128 rows x 8 float4, coalesced, xor-swizzled
        #pragma unroll
        for (int it = 0; it < 8; it++) {
            int idx = it * 128 + t, row = idx >> 3, s4 = idx & 7;
            float4 b = *(const float4*)(g_bias + (bias_qbase + row) * TOK + kt * 32 + s4 * 4);
            bsm[row][s4 ^ (row & 7)] = b;
        }
        __syncthreads();
        if (resq && kt < 12) {                       // rec keys (12*32 = 384)
            if (m == 0) attn_tile32<1>(t, dual, q2, mx, sm, accR, accA, ksm, vsm, bsm);
            else        attn_tile32<2>(t, dual, q2, mx, sm, accR, accA, ksm, vsm, bsm);
        } else          attn_tile32<0>(t, dual, q2, mx, sm, accR, accA, ksm, vsm, bsm);
        __syncthreads();
    }

    float inv = 1.0f / sm;
    if (resq) {
        // atom-key PV -> g_atmPV[m][h][qtok][*]
        store_pv(g_atmPV + (((size_t)m * NH + h) * NRES + qtok) * AC, accA, inv);
        if (m == 0)  // rec-key PV -> g_resPV[h][qtok][*]
            store_pv(g_resPV + ((size_t)h * NRES + qtok) * AC, accR, inv);
    } else {
        store_pv(g_ligPV + (((size_t)m * NH + h) * NATM + (qtok - NRES)) * AC, accA, inv);
    }
}

// ---------------- K4: combine + final projections ----------------
__global__ __launch_bounds__(256) void k_out(const float* __restrict__ wrf, const float* __restrict__ brf,
                                             const float* __restrict__ wlf, const float* __restrict__ blf,
                                             float* __restrict__ out) {
    __shared__ __align__(16) float xs_t[C1][18];
    int tile = blockIdx.x, t = threadIdx.x;
    bool isrec = tile < 24;
    const float* w = isrec ? wrf : wlf;
    const float* bb = isrec ? brf : blf;
    int row0 = isrec ? tile * 16 : (tile - 24) * 16;
    // gather PV from head-major scratch: idx -> (h, r, c4)
    #pragma unroll
    for (int k = 0; k < 4; k++) {
        int idx = k * 256 + t;
        int c4 = idx & 7, r = (idx >> 3) & 15, h = idx >> 7;
        float4 v;
        if (isrec) {
            size_t off = ((size_t)h * NRES + row0 + r) * 8 + c4;   // float4 units
            v = ((const float4*)g_resPV)[off];
            #pragma unroll
            for (int m = 0; m < NCEP; m++) {
                float4 a = ((const float4*)g_atmPV)[(((size_t)m * NH + h) * NRES + row0 + r) * 8 + c4];
                v.x += 0.25f * a.x; v.y += 0.25f * a.y;
                v.z += 0.25f * a.z; v.w += 0.25f * a.w;
            }
        } else {
            int lrow = row0 + r;
            int m = lrow / NATM, q = lrow - m * NATM;
            v = ((const float4*)g_ligPV)[(((size_t)m * NH + h) * NATM + q) * 8 + c4];
        }
        // flat col = c*8 + h, c = 4*c4 + e
        xs_t[(4 * c4 + 0) * 8 + h][r] = v.x;
        xs_t[(4 * c4 + 1) * 8 + h][r] = v.y;
        xs_t[(4 * c4 + 2) * 8 + h][r] = v.z;
        xs_t[(4 * c4 + 3) * 8 + h][r] = v.w;
    }
    __syncthreads();
    int o = t;
    ull acc[8];
    #pragma unroll
    for (int r2 = 0; r2 < 8; r2++) acc[r2] = 0ull;
    const float* wc = w + o;
    #pragma unroll 4
    for (int i = 0; i < C1; i++) {
        float wv = wc[(size_t)i * 256];
        ull w2 = pack2(wv, wv);
        #pragma unroll
        for (int r2 = 0; r2 < 8; r2++) ffma2(acc[r2], *(const ull*)&xs_t[i][2 * r2], w2);
    }
    float bv = bb[o];
    float* ob = out + (isrec ? (size_t)0 : (size_t)NRES * C1);
    #pragma unroll
    for (int r2 = 0; r2 < 8; r2++) {
        float2 a = unpack2(acc[r2]);
        ob[(size_t)(row0 + 2 * r2) * C1 + o] = a.x + bv;
        ob[(size_t)(row0 + 2 * r2 + 1) * C1 + o] = a.y + bv;
    }
}

// ---------------- launch ----------------
extern "C" void kernel_launch(void* const* d_in, const int* in_sizes, int n_in,
                              void* d_out, int out_size) {
    const float* rec = (const float*)d_in[0];
    const float* lig = (const float*)d_in[1];
    const float* pair = (const float*)d_in[2];
    const float* ln_g = (const float*)d_in[3];
    const float* ln_b = (const float*)d_in[4];
    const float* wrq = (const float*)d_in[5];
    const float* wrk = (const float*)d_in[6];
    const float* wrv = (const float*)d_in[7];
    const float* wlq = (const float*)d_in[8];
    const float* wlk = (const float*)d_in[9];
    const float* wlv = (const float*)d_in[10];
    const float* wrr = (const float*)d_in[11];
    const float* wll = (const float*)d_in[12];
    const float* wrl = (const float*)d_in[13];
    const float* wlr = (const float*)d_in[14];
    const float* wrf = (const float*)d_in[15];
    const float* brf = (const float*)d_in[16];
    const float* wlf = (const float*)d_in[17];
    const float* blf = (const float*)d_in[18];
    float* out = (float*)d_out;

    k_bias<<<TOK, 256>>>(pair, wrr, wll, wrl, wlr);
    k_ln<<<NROWS, 256>>>(rec, lig, ln_g, ln_b);
    k_proj<<<dim3(NROWS / 16, 3), 256>>>(wrq, wrk, wrv, wlq, wlk, wlv);
    k_attn<<<dim3(8, NH, NCEP), 128>>>();
    k_out<<<24 + (NCEP * NATM) / 16, 256>>>(wrf, brf, wlf, blf, out);
}